// round 11
// baseline (speedup 1.0000x reference)
#include <cuda_runtime.h>
#include <cuda_bf16.h>
#include <cstdint>
#include <math.h>

#define DM    1024
#define NB    4
#define NSEQ  2048
#define NTOK  8192
#define NH    16
#define HD    64
#define BHN   64
#define NQKV  3072
#define LN_EPS 1e-5f

// ---------------- bf16 staging (device globals; no allocs allowed) ----------
__device__ __nv_bfloat16 g_znB[NTOK * DM];        // LN output bf16
__device__ __nv_bfloat16 g_wqkvT[NQKV * DM];      // w_qkv^T bf16 [out][in]
__device__ __nv_bfloat16 g_wprojT[DM * DM];       // w_proj^T bf16 [out][in]
__device__ __nv_bfloat16 g_q[BHN * NSEQ * HD];    // [bh][n][d], pre-scaled 1/8
__device__ __nv_bfloat16 g_k[BHN * NSEQ * HD];    // [bh][n][d]
__device__ __nv_bfloat16 g_v[BHN * NSEQ * HD];    // [bh][n][d]
__device__ __nv_bfloat16 g_oB[NTOK * DM];         // attn out bf16 [b][n][h*d]

// ---------------- baseline-PTX helpers (NO tcgen05 — compute_103 target) ----
__device__ __forceinline__ uint32_t s2u(const void* p) {
    return (uint32_t)__cvta_generic_to_shared(p);
}
__device__ __forceinline__ void cp16(uint32_t s, const void* g) {
    asm volatile("cp.async.cg.shared.global [%0], [%1], 16;" :: "r"(s), "l"(g));
}
#define CP_COMMIT() asm volatile("cp.async.commit_group;" ::: "memory")
#define CP_WAIT(n)  asm volatile("cp.async.wait_group %0;" :: "n"(n) : "memory")

__device__ __forceinline__ void ldsm4(uint32_t* r, uint32_t a) {
    asm volatile("ldmatrix.sync.aligned.m8n8.x4.shared.b16 {%0,%1,%2,%3}, [%4];"
                 : "=r"(r[0]), "=r"(r[1]), "=r"(r[2]), "=r"(r[3]) : "r"(a));
}
__device__ __forceinline__ void ldsm4t(uint32_t* r, uint32_t a) {
    asm volatile("ldmatrix.sync.aligned.m8n8.x4.trans.shared.b16 {%0,%1,%2,%3}, [%4];"
                 : "=r"(r[0]), "=r"(r[1]), "=r"(r[2]), "=r"(r[3]) : "r"(a));
}
__device__ __forceinline__ void mma16816(float* d, const uint32_t* a, const uint32_t* b) {
    asm volatile("mma.sync.aligned.m16n8k16.row.col.f32.bf16.bf16.f32 "
                 "{%0,%1,%2,%3}, {%4,%5,%6,%7}, {%8,%9}, {%0,%1,%2,%3};"
                 : "+f"(d[0]), "+f"(d[1]), "+f"(d[2]), "+f"(d[3])
                 : "r"(a[0]), "r"(a[1]), "r"(a[2]), "r"(a[3]), "r"(b[0]), "r"(b[1]));
}
#define SWZ128(row, chunk) ((row) * 128 + ((((chunk) ^ ((row) & 7))) << 4))

// ---------------- LayerNorm -> bf16 -----------------------------------------
__global__ __launch_bounds__(256) void ln_kernel(const float* __restrict__ z,
                                                 const float* __restrict__ gamma,
                                                 const float* __restrict__ beta) {
    __shared__ float rs[8], rss[8];
    const int row = blockIdx.x, t = threadIdx.x;
    const float4 v = *(const float4*)(z + (size_t)row * DM + t * 4);
    float s = v.x + v.y + v.z + v.w;
    float ss = v.x * v.x + v.y * v.y + v.z * v.z + v.w * v.w;
#pragma unroll
    for (int off = 16; off; off >>= 1) {
        s  += __shfl_xor_sync(~0u, s, off);
        ss += __shfl_xor_sync(~0u, ss, off);
    }
    const int w = t >> 5, lane = t & 31;
    if (lane == 0) { rs[w] = s; rss[w] = ss; }
    __syncthreads();
    if (w == 0) {
        float s2 = (lane < 8) ? rs[lane] : 0.f, ss2 = (lane < 8) ? rss[lane] : 0.f;
#pragma unroll
        for (int off = 4; off; off >>= 1) {
            s2  += __shfl_xor_sync(~0u, s2, off, 8);
            ss2 += __shfl_xor_sync(~0u, ss2, off, 8);
        }
        if (lane == 0) { rs[0] = s2; rss[0] = ss2; }
    }
    __syncthreads();
    const float mean = rs[0] * (1.f / DM);
    const float var  = rss[0] * (1.f / DM) - mean * mean;
    const float inv  = rsqrtf(var + LN_EPS);
    const float4 g = *(const float4*)(gamma + t * 4);
    const float4 b = *(const float4*)(beta + t * 4);
    __nv_bfloat162 p0 = __floats2bfloat162_rn((v.x - mean) * inv * g.x + b.x,
                                              (v.y - mean) * inv * g.y + b.y);
    __nv_bfloat162 p1 = __floats2bfloat162_rn((v.z - mean) * inv * g.z + b.z,
                                              (v.w - mean) * inv * g.w + b.w);
    __nv_bfloat162* dst = (__nv_bfloat162*)(g_znB + (size_t)row * DM + t * 4);
    dst[0] = p0; dst[1] = p1;
}

// ---------------- weight transpose + fp32->bf16 -----------------------------
__global__ __launch_bounds__(256) void tcvt_kernel(const float* __restrict__ w,
                                                   __nv_bfloat16* __restrict__ wT,
                                                   int K, int N) {
    __shared__ float tile[32][33];
    const int n0 = blockIdx.x * 32, k0 = blockIdx.y * 32;
    for (int i = threadIdx.y; i < 32; i += 8)
        tile[i][threadIdx.x] = w[(size_t)(k0 + i) * N + n0 + threadIdx.x];
    __syncthreads();
    for (int i = threadIdx.y; i < 32; i += 8)
        wT[(size_t)(n0 + i) * K + k0 + threadIdx.x] = __float2bfloat16(tile[threadIdx.x][i]);
}

// ---------------- templated 128xBN GEMM core (3-stage, K-chunk 64) ----------
// WC = warp columns. Warps = 2 x WC, threads = 64*WC, BN = 32*WC.
// cp.async issues for stage kt+2 are interleaved into the 4 k16 MMA steps.
template<int WC>
__device__ __forceinline__ void gemm_core(const __nv_bfloat16* __restrict__ gA,
                                          const __nv_bfloat16* __restrict__ gB,
                                          int m0, int n0, float acc[4][4][4]) {
    constexpr int NT = 64 * WC;
    constexpr int BN = 32 * WC;
    constexpr int ABYTES = 16384;
    constexpr int STAGE  = ABYTES + BN * 128;
    constexpr int TOT    = (128 + BN) * 8;     // 16B chunks per stage
    constexpr int NLOAD  = (TOT + NT - 1) / NT;
    extern __shared__ char sm[];
    const uint32_t sb = s2u(sm);
    const int t = threadIdx.x, lane = t & 31, wid = t >> 5;
    const int wm = (wid / WC) * 64, wn = (wid % WC) * 32;
#pragma unroll
    for (int i = 0; i < 4; i++)
#pragma unroll
        for (int j = 0; j < 4; j++)
#pragma unroll
            for (int c = 0; c < 4; c++) acc[i][j][c] = 0.f;

    auto load_part = [&](int kt, int slot, int i0, int i1) {
        const int k0 = kt * 64;
        const uint32_t base = sb + slot * STAGE;
#pragma unroll
        for (int i = i0; i < i1; i++) {
            const int idx = t + i * NT;
            if ((TOT % NT == 0) || idx < TOT) {
                const int row = idx >> 3, ch = idx & 7;
                if (row < 128)
                    cp16(base + SWZ128(row, ch),
                         gA + (size_t)(m0 + row) * DM + k0 + ch * 8);
                else
                    cp16(base + ABYTES + SWZ128((row - 128), ch),
                         gB + (size_t)(n0 + row - 128) * DM + k0 + ch * 8);
            }
        }
    };
    load_part(0, 0, 0, NLOAD); CP_COMMIT();
    load_part(1, 1, 0, NLOAD); CP_COMMIT();
    for (int kt = 0; kt < 16; kt++) {
        if (kt < 15) CP_WAIT(1); else CP_WAIT(0);
        __syncthreads();                       // stage kt ready; slot (kt+2)%3 free
        const bool pf = (kt + 2 < 16);
        const int pslot = (kt + 2) % 3;
        const uint32_t Ab = sb + (kt % 3) * STAGE;
        const uint32_t Bb = Ab + ABYTES;
#pragma unroll
        for (int k16 = 0; k16 < 4; k16++) {
            if (pf) load_part(kt + 2, pslot, (NLOAD * k16) / 4, (NLOAD * (k16 + 1)) / 4);
            uint32_t af[4][4], bfr[2][4];
#pragma unroll
            for (int mi = 0; mi < 4; mi++)
                ldsm4(af[mi], Ab + SWZ128(wm + mi * 16 + (lane & 15),
                                          k16 * 2 + (lane >> 4)));
#pragma unroll
            for (int g = 0; g < 2; g++)
                ldsm4(bfr[g], Bb + SWZ128(wn + g * 16 + (lane & 7) + ((lane >> 4) << 3),
                                          k16 * 2 + ((lane >> 3) & 1)));
#pragma unroll
            for (int mi = 0; mi < 4; mi++)
#pragma unroll
                for (int nj = 0; nj < 4; nj++)
                    mma16816(acc[mi][nj], af[mi], &bfr[nj >> 1][(nj & 1) * 2]);
        }
        if (pf) CP_COMMIT();
    }
}

// ---------------- QKV GEMM: N-tile 192 == one head; coalesced epilogue ------
// smem: 3 x (16384 + 24576) = 122880; epilogue staging reuses it (51200 B).
#define QKV_SMEM 122880
__global__ __launch_bounds__(384, 1) void qkv_mm() {
    float acc[4][4][4];
    const int h = blockIdx.x, m0 = blockIdx.y * 128;
    gemm_core<6>(g_znB, g_wqkvT, m0, h * 192, acc);

    extern __shared__ char sm[];
    const int t = threadIdx.x, lane = t & 31, wid = t >> 5;
    const int wm = (wid / 6) * 64, wn = (wid % 6) * 32;
    __syncthreads();                           // all MMA reads of smem done
    // stage bf16 tile [128 m][192 c], pitch 400 B (conflict-free stores)
#pragma unroll
    for (int mi = 0; mi < 4; mi++)
#pragma unroll
        for (int nj = 0; nj < 4; nj++)
#pragma unroll
            for (int half = 0; half < 2; half++) {
                const int er = wm + mi * 16 + (lane >> 2) + half * 8;
                const int ec = wn + nj * 8 + (lane & 3) * 2;
                __nv_bfloat162 p = __floats2bfloat162_rn(acc[mi][nj][half * 2],
                                                         acc[mi][nj][half * 2 + 1]);
                *(__nv_bfloat162*)(sm + er * 400 + ec * 2) = p;
            }
    __syncthreads();
    // gather stride-3, write coalesced 16B vectors. tasks = 128m x 3sel x 8chunks
#pragma unroll
    for (int i = 0; i < 8; i++) {
        const int task = t + i * 384;
        const int chunk = task & 7;
        const int ms = task >> 3;
        const int sel = ms % 3;
        const int m = ms / 3;
        const int mg = m0 + m, bi = mg >> 11, ni = mg & 2047;
        const int bh = bi * NH + h;
        __align__(16) __nv_bfloat16 tmp[8];
#pragma unroll
        for (int j = 0; j < 8; j++) {
            __nv_bfloat16 v = *(const __nv_bfloat16*)(sm + m * 400 +
                                                      (3 * (chunk * 8 + j) + sel) * 2);
            tmp[j] = (sel == 0) ? __float2bfloat16(__bfloat162float(v) * 0.125f) : v;
        }
        __nv_bfloat16* dst = (sel == 0 ? g_q : sel == 1 ? g_k : g_v)
                             + ((size_t)bh * NSEQ + ni) * HD + chunk * 8;
        *(uint4*)dst = *(const uint4*)tmp;
    }
}

// ---------------- Proj GEMM + bias + residual --------------------------------
#define PROJ_SMEM 98304
__global__ __launch_bounds__(256, 2) void proj_mm(const float* __restrict__ bias,
                                                  const float* __restrict__ z,
                                                  float* __restrict__ out) {
    float acc[4][4][4];
    const int m0 = blockIdx.y * 128, n0 = blockIdx.x * 128;
    gemm_core<4>(g_oB, g_wprojT, m0, n0, acc);
    const int t = threadIdx.x, lane = t & 31, wid = t >> 5;
    const int wm = (wid >> 2) * 64, wn = (wid & 3) * 32;
#pragma unroll
    for (int mi = 0; mi < 4; mi++) {
        const int r = m0 + wm + mi * 16 + (lane >> 2);
#pragma unroll
        for (int nj = 0; nj < 4; nj++) {
            const int n = n0 + wn + nj * 8 + (lane & 3) * 2;
            const float2 b2 = *(const float2*)(bias + n);
            {
                const float2 z2 = *(const float2*)(z + (size_t)r * DM + n);
                float2 o; o.x = acc[mi][nj][0] + b2.x + z2.x;
                          o.y = acc[mi][nj][1] + b2.y + z2.y;
                *(float2*)(out + (size_t)r * DM + n) = o;
            }
            {
                const float2 z2 = *(const float2*)(z + (size_t)(r + 8) * DM + n);
                float2 o; o.x = acc[mi][nj][2] + b2.x + z2.x;
                          o.y = acc[mi][nj][3] + b2.y + z2.y;
                *(float2*)(out + (size_t)(r + 8) * DM + n) = o;
            }
        }
    }
}

// ---------------- Flash attention (mma.sync, 3-stage, 1 sync/tile) ----------
// smem: Q@0 (16KB); stage s @ 16384 + s*32768: K 16KB, V 16KB.  Total 114688.
#define ATT_SMEM (16384 + 3 * 32768)
__global__ __launch_bounds__(256) void attn_mm() {
    extern __shared__ char sm[];
    const uint32_t sb = s2u(sm);
    const int t = threadIdx.x, lane = t & 31, wid = t >> 5;
    const int bh = blockIdx.y, q0 = blockIdx.x * 128;
    const __nv_bfloat16* Qp = g_q + ((size_t)bh * NSEQ + q0) * HD;
    const __nv_bfloat16* Kp = g_k + (size_t)bh * NSEQ * HD;
    const __nv_bfloat16* Vp = g_v + (size_t)bh * NSEQ * HD;

    auto load_tile = [&](uint32_t sbase, const __nv_bfloat16* gp) {
#pragma unroll
        for (int i = 0; i < 4; i++) {
            const int idx = t + i * 256, row = idx >> 3, ch = idx & 7;
            cp16(sbase + SWZ128(row, ch), gp + (size_t)row * HD + ch * 8);
        }
    };
    auto load_kv = [&](int kt, int slot) {
        load_tile(sb + 16384 + slot * 32768, Kp + (size_t)kt * 128 * HD);
        load_tile(sb + 16384 + slot * 32768 + 16384, Vp + (size_t)kt * 128 * HD);
    };
    load_tile(sb, Qp);
    load_kv(0, 0); CP_COMMIT();
    load_kv(1, 1); CP_COMMIT();

    float o[8][4];
#pragma unroll
    for (int i = 0; i < 8; i++)
#pragma unroll
        for (int c = 0; c < 4; c++) o[i][c] = 0.f;
    float l0 = 0.f, l1 = 0.f;
    uint32_t qf[4][4];

    for (int kt = 0; kt < 16; kt++) {
        if (kt < 15) CP_WAIT(1); else CP_WAIT(0);
        __syncthreads();                 // stage kt ready; slot (kt+2)%3 is free
        if (kt + 2 < 16) { load_kv(kt + 2, (kt + 2) % 3); CP_COMMIT(); }
        if (kt == 0) {
#pragma unroll
            for (int kk = 0; kk < 4; kk++)
                ldsm4(qf[kk], sb + SWZ128(wid * 16 + (lane & 15), kk * 2 + (lane >> 4)));
        }
        const uint32_t Kb = sb + 16384 + (kt % 3) * 32768;
        const uint32_t Vb = Kb + 16384;
#pragma unroll
        for (int half = 0; half < 2; half++) {
            float s[8][4];
#pragma unroll
            for (int i = 0; i < 8; i++)
#pragma unroll
                for (int c = 0; c < 4; c++) s[i][c] = 0.f;
#pragma unroll
            for (int kk = 0; kk < 4; kk++) {          // S = Q @ K^T (16q x 64k)
                uint32_t bfr[4][4];
#pragma unroll
                for (int g = 0; g < 4; g++)
                    ldsm4(bfr[g], Kb + SWZ128(half * 64 + g * 16 + (lane & 7) +
                                              ((lane >> 4) << 3),
                                              kk * 2 + ((lane >> 3) & 1)));
#pragma unroll
                for (int nj = 0; nj < 8; nj++)
                    mma16816(s[nj], qf[kk], &bfr[nj >> 1][(nj & 1) * 2]);
            }
            uint32_t pf[4][4];                        // exp + pack P into A-frags
#pragma unroll
            for (int nj = 0; nj < 8; nj++) {
                const float p0 = __expf(s[nj][0]), p1 = __expf(s[nj][1]);
                const float p2 = __expf(s[nj][2]), p3 = __expf(s[nj][3]);
                l0 += p0 + p1; l1 += p2 + p3;
                const __nv_bfloat162 u = __floats2bfloat162_rn(p0, p1);
                const __nv_bfloat162 v = __floats2bfloat162_rn(p2, p3);
                pf[nj >> 1][(nj & 1) * 2 + 0] = *(const uint32_t*)&u;
                pf[nj >> 1][(nj & 1) * 2 + 1] = *(const uint32_t*)&v;
            }
#pragma unroll
            for (int kk = 0; kk < 4; kk++) {          // O += P @ V (k=16 keys)
                const int kb = (half * 4 + kk) * 16;
                uint32_t vf[4][4];
#pragma unroll
                for (int g = 0; g < 4; g++)
                    ldsm4t(vf[g], Vb + SWZ128(kb + (lane & 7) + (((lane >> 3) & 1) << 3),
                                              g * 2 + (lane >> 4)));
#pragma unroll
                for (int nj = 0; nj < 8; nj++)
                    mma16816(o[nj], pf[kk], &vf[nj >> 1][(nj & 1) * 2]);
            }
        }
    }
    l0 += __shfl_xor_sync(~0u, l0, 1); l0 += __shfl_xor_sync(~0u, l0, 2);
    l1 += __shfl_xor_sync(~0u, l1, 1); l1 += __shfl_xor_sync(~0u, l1, 2);
    const float i0 = 1.f / l0, i1 = 1.f / l1;
    const int bi = bh >> 4, h = bh & 15;
    const int r = q0 + wid * 16 + (lane >> 2);
#pragma unroll
    for (int nj = 0; nj < 8; nj++) {
        const int d = nj * 8 + (lane & 3) * 2;
        const __nv_bfloat162 u = __floats2bfloat162_rn(o[nj][0] * i0, o[nj][1] * i0);
        const __nv_bfloat162 v = __floats2bfloat162_rn(o[nj][2] * i1, o[nj][3] * i1);
        *(__nv_bfloat162*)(g_oB + (size_t)(bi * NSEQ + r) * DM + h * HD + d) = u;
        *(__nv_bfloat162*)(g_oB + (size_t)(bi * NSEQ + r + 8) * DM + h * HD + d) = v;
    }
}

// ---------------- launch ----------------------------------------------------
extern "C" void kernel_launch(void* const* d_in, const int* in_sizes, int n_in,
                              void* d_out, int out_size) {
    const float* z      = (const float*)d_in[0];
    const float* gamma  = (const float*)d_in[1];
    const float* beta   = (const float*)d_in[2];
    const float* w_qkv  = (const float*)d_in[3];
    const float* w_proj = (const float*)d_in[4];
    const float* b_proj = (const float*)d_in[5];
    float* out = (float*)d_out;

    cudaFuncSetAttribute(attn_mm, cudaFuncAttributeMaxDynamicSharedMemorySize, ATT_SMEM);
    cudaFuncSetAttribute(qkv_mm,  cudaFuncAttributeMaxDynamicSharedMemorySize, QKV_SMEM);
    cudaFuncSetAttribute(proj_mm, cudaFuncAttributeMaxDynamicSharedMemorySize, PROJ_SMEM);

    __nv_bfloat16 *wqT, *wpT;
    cudaGetSymbolAddress((void**)&wqT, g_wqkvT);
    cudaGetSymbolAddress((void**)&wpT, g_wprojT);

    ln_kernel<<<NTOK, 256>>>(z, gamma, beta);
    tcvt_kernel<<<dim3(NQKV / 32, DM / 32), dim3(32, 8)>>>(w_qkv, wqT, DM, NQKV);
    tcvt_kernel<<<dim3(DM / 32, DM / 32), dim3(32, 8)>>>(w_proj, wpT, DM, DM);
    qkv_mm<<<dim3(NH, NTOK / 128), 384, QKV_SMEM>>>();
    attn_mm<<<dim3(NSEQ / 128, BHN), 256, ATT_SMEM>>>();
    proj_mm<<<dim3(DM / 128, NTOK / 128), 256, PROJ_SMEM>>>(b_proj, z, out);
}

// round 12
// speedup vs baseline: 1.5069x; 1.5069x over previous
#include <cuda_runtime.h>
#include <cuda_bf16.h>
#include <cstdint>
#include <math.h>

#define DM    1024
#define NB    4
#define NSEQ  2048
#define NTOK  8192
#define NH    16
#define HD    64
#define BHN   64
#define NQKV  3072
#define LN_EPS 1e-5f

// ---------------- bf16 staging (device globals; no allocs allowed) ----------
__device__ __nv_bfloat16 g_znB[NTOK * DM];        // LN output bf16
__device__ __nv_bfloat16 g_wqkvT[NQKV * DM];      // w_qkv^T bf16 [out][in]
__device__ __nv_bfloat16 g_wprojT[DM * DM];       // w_proj^T bf16 [out][in]
__device__ __nv_bfloat16 g_q[BHN * NSEQ * HD];    // [bh][n][d], pre-scaled 1/8
__device__ __nv_bfloat16 g_k[BHN * NSEQ * HD];    // [bh][n][d]
__device__ __nv_bfloat16 g_v[BHN * NSEQ * HD];    // [bh][n][d]
__device__ __nv_bfloat16 g_oB[NTOK * DM];         // attn out bf16 [b][n][h*d]

// ---------------- baseline-PTX helpers (NO tcgen05 — compute_103 target) ----
__device__ __forceinline__ uint32_t s2u(const void* p) {
    return (uint32_t)__cvta_generic_to_shared(p);
}
__device__ __forceinline__ void cp16(uint32_t s, const void* g) {
    asm volatile("cp.async.cg.shared.global [%0], [%1], 16;" :: "r"(s), "l"(g));
}
#define CP_COMMIT() asm volatile("cp.async.commit_group;" ::: "memory")
#define CP_WAIT(n)  asm volatile("cp.async.wait_group %0;" :: "n"(n) : "memory")

__device__ __forceinline__ void ldsm4(uint32_t* r, uint32_t a) {
    asm volatile("ldmatrix.sync.aligned.m8n8.x4.shared.b16 {%0,%1,%2,%3}, [%4];"
                 : "=r"(r[0]), "=r"(r[1]), "=r"(r[2]), "=r"(r[3]) : "r"(a));
}
__device__ __forceinline__ void ldsm4t(uint32_t* r, uint32_t a) {
    asm volatile("ldmatrix.sync.aligned.m8n8.x4.trans.shared.b16 {%0,%1,%2,%3}, [%4];"
                 : "=r"(r[0]), "=r"(r[1]), "=r"(r[2]), "=r"(r[3]) : "r"(a));
}
__device__ __forceinline__ void mma16816(float* d, const uint32_t* a, const uint32_t* b) {
    asm volatile("mma.sync.aligned.m16n8k16.row.col.f32.bf16.bf16.f32 "
                 "{%0,%1,%2,%3}, {%4,%5,%6,%7}, {%8,%9}, {%0,%1,%2,%3};"
                 : "+f"(d[0]), "+f"(d[1]), "+f"(d[2]), "+f"(d[3])
                 : "r"(a[0]), "r"(a[1]), "r"(a[2]), "r"(a[3]), "r"(b[0]), "r"(b[1]));
}
#define SWZ128(row, chunk) ((row) * 128 + ((((chunk) ^ ((row) & 7))) << 4))

// ---------------- LayerNorm -> bf16 -----------------------------------------
__global__ __launch_bounds__(256) void ln_kernel(const float* __restrict__ z,
                                                 const float* __restrict__ gamma,
                                                 const float* __restrict__ beta) {
    __shared__ float rs[8], rss[8];
    const int row = blockIdx.x, t = threadIdx.x;
    const float4 v = *(const float4*)(z + (size_t)row * DM + t * 4);
    float s = v.x + v.y + v.z + v.w;
    float ss = v.x * v.x + v.y * v.y + v.z * v.z + v.w * v.w;
#pragma unroll
    for (int off = 16; off; off >>= 1) {
        s  += __shfl_xor_sync(~0u, s, off);
        ss += __shfl_xor_sync(~0u, ss, off);
    }
    const int w = t >> 5, lane = t & 31;
    if (lane == 0) { rs[w] = s; rss[w] = ss; }
    __syncthreads();
    if (w == 0) {
        float s2 = (lane < 8) ? rs[lane] : 0.f, ss2 = (lane < 8) ? rss[lane] : 0.f;
#pragma unroll
        for (int off = 4; off; off >>= 1) {
            s2  += __shfl_xor_sync(~0u, s2, off, 8);
            ss2 += __shfl_xor_sync(~0u, ss2, off, 8);
        }
        if (lane == 0) { rs[0] = s2; rss[0] = ss2; }
    }
    __syncthreads();
    const float mean = rs[0] * (1.f / DM);
    const float var  = rss[0] * (1.f / DM) - mean * mean;
    const float inv  = rsqrtf(var + LN_EPS);
    const float4 g = *(const float4*)(gamma + t * 4);
    const float4 b = *(const float4*)(beta + t * 4);
    __nv_bfloat162 p0 = __floats2bfloat162_rn((v.x - mean) * inv * g.x + b.x,
                                              (v.y - mean) * inv * g.y + b.y);
    __nv_bfloat162 p1 = __floats2bfloat162_rn((v.z - mean) * inv * g.z + b.z,
                                              (v.w - mean) * inv * g.w + b.w);
    __nv_bfloat162* dst = (__nv_bfloat162*)(g_znB + (size_t)row * DM + t * 4);
    dst[0] = p0; dst[1] = p1;
}

// ---------------- weight transpose + fp32->bf16 -----------------------------
__global__ __launch_bounds__(256) void tcvt_kernel(const float* __restrict__ w,
                                                   __nv_bfloat16* __restrict__ wT,
                                                   int K, int N) {
    __shared__ float tile[32][33];
    const int n0 = blockIdx.x * 32, k0 = blockIdx.y * 32;
    for (int i = threadIdx.y; i < 32; i += 8)
        tile[i][threadIdx.x] = w[(size_t)(k0 + i) * N + n0 + threadIdx.x];
    __syncthreads();
    for (int i = threadIdx.y; i < 32; i += 8)
        wT[(size_t)(n0 + i) * K + k0 + threadIdx.x] = __float2bfloat16(tile[threadIdx.x][i]);
}

// ---------------- templated 128xBN GEMM core (NS-stage, K-chunk 64) ---------
// WC = warp columns. Warps = 2 x WC, threads = 64*WC, BN = 32*WC.
// Burst cp.async per stage (one commit), one __syncthreads per chunk.
template<int WC, int NS>
__device__ __forceinline__ void gemm_core(const __nv_bfloat16* __restrict__ gA,
                                          const __nv_bfloat16* __restrict__ gB,
                                          int m0, int n0, float acc[4][4][4]) {
    constexpr int NT = 64 * WC;
    constexpr int BN = 32 * WC;
    constexpr int ABYTES = 16384;
    constexpr int STAGE  = ABYTES + BN * 128;
    constexpr int TOT    = (128 + BN) * 8;     // 16B chunks per stage
    constexpr int NLOAD  = (TOT + NT - 1) / NT;
    extern __shared__ char sm[];
    const uint32_t sb = s2u(sm);
    const int t = threadIdx.x, lane = t & 31, wid = t >> 5;
    const int wm = (wid / WC) * 64, wn = (wid % WC) * 32;
#pragma unroll
    for (int i = 0; i < 4; i++)
#pragma unroll
        for (int j = 0; j < 4; j++)
#pragma unroll
            for (int c = 0; c < 4; c++) acc[i][j][c] = 0.f;

    auto load_stage = [&](int kt, int slot) {
        const int k0 = kt * 64;
        const uint32_t base = sb + slot * STAGE;
#pragma unroll
        for (int i = 0; i < NLOAD; i++) {
            const int idx = t + i * NT;
            if ((TOT % NT == 0) || idx < TOT) {
                const int row = idx >> 3, ch = idx & 7;
                if (row < 128)
                    cp16(base + SWZ128(row, ch),
                         gA + (size_t)(m0 + row) * DM + k0 + ch * 8);
                else
                    cp16(base + ABYTES + SWZ128((row - 128), ch),
                         gB + (size_t)(n0 + row - 128) * DM + k0 + ch * 8);
            }
        }
    };
#pragma unroll
    for (int s = 0; s < NS - 1; s++) { load_stage(s, s); CP_COMMIT(); }
    for (int kt = 0; kt < 16; kt++) {
        // stage kt must be complete; allow min(NS-2, 15-kt) groups pending
        if constexpr (NS == 4) {
            if (kt < 14) CP_WAIT(2); else if (kt == 14) CP_WAIT(1); else CP_WAIT(0);
        } else {
            if (kt < 15) CP_WAIT(1); else CP_WAIT(0);
        }
        __syncthreads();                 // stage kt ready; slot (kt+NS-1)%NS free
        if (kt + NS - 1 < 16) { load_stage(kt + NS - 1, (kt + NS - 1) % NS); CP_COMMIT(); }
        const uint32_t Ab = sb + (kt % NS) * STAGE;
        const uint32_t Bb = Ab + ABYTES;
#pragma unroll
        for (int k16 = 0; k16 < 4; k16++) {
            uint32_t af[4][4], bfr[2][4];
#pragma unroll
            for (int mi = 0; mi < 4; mi++)
                ldsm4(af[mi], Ab + SWZ128(wm + mi * 16 + (lane & 15),
                                          k16 * 2 + (lane >> 4)));
#pragma unroll
            for (int g = 0; g < 2; g++)
                ldsm4(bfr[g], Bb + SWZ128(wn + g * 16 + (lane & 7) + ((lane >> 4) << 3),
                                          k16 * 2 + ((lane >> 3) & 1)));
#pragma unroll
            for (int mi = 0; mi < 4; mi++)
#pragma unroll
                for (int nj = 0; nj < 4; nj++)
                    mma16816(acc[mi][nj], af[mi], &bfr[nj >> 1][(nj & 1) * 2]);
        }
    }
}

// ---------------- QKV GEMM: N-tile 192 == one head; coalesced epilogue ------
// smem: 4 stages x (16384 + 24576) = 163840; epilogue staging reuses 51200 B.
#define QKV_SMEM 163840
__global__ __launch_bounds__(384, 1) void qkv_mm() {
    float acc[4][4][4];
    const int h = blockIdx.x, m0 = blockIdx.y * 128;
    gemm_core<6, 4>(g_znB, g_wqkvT, m0, h * 192, acc);

    extern __shared__ char sm[];
    const int t = threadIdx.x, lane = t & 31, wid = t >> 5;
    const int wm = (wid / 6) * 64, wn = (wid % 6) * 32;
    __syncthreads();                           // all MMA reads of smem done
    // stage bf16 tile [128 m][192 c], pitch 400 B (conflict-free stores)
#pragma unroll
    for (int mi = 0; mi < 4; mi++)
#pragma unroll
        for (int nj = 0; nj < 4; nj++)
#pragma unroll
            for (int half = 0; half < 2; half++) {
                const int er = wm + mi * 16 + (lane >> 2) + half * 8;
                const int ec = wn + nj * 8 + (lane & 3) * 2;
                __nv_bfloat162 p = __floats2bfloat162_rn(acc[mi][nj][half * 2],
                                                         acc[mi][nj][half * 2 + 1]);
                *(__nv_bfloat162*)(sm + er * 400 + ec * 2) = p;
            }
    __syncthreads();
    // gather stride-3, write coalesced 16B vectors. tasks = 128m x 3sel x 8chunks
#pragma unroll
    for (int i = 0; i < 8; i++) {
        const int task = t + i * 384;
        const int chunk = task & 7;
        const int ms = task >> 3;
        const int sel = ms % 3;
        const int m = ms / 3;
        const int mg = m0 + m, bi = mg >> 11, ni = mg & 2047;
        const int bh = bi * NH + h;
        __align__(16) __nv_bfloat16 tmp[8];
#pragma unroll
        for (int j = 0; j < 8; j++) {
            __nv_bfloat16 v = *(const __nv_bfloat16*)(sm + m * 400 +
                                                      (3 * (chunk * 8 + j) + sel) * 2);
            tmp[j] = (sel == 0) ? __float2bfloat16(__bfloat162float(v) * 0.125f) : v;
        }
        __nv_bfloat16* dst = (sel == 0 ? g_q : sel == 1 ? g_k : g_v)
                             + ((size_t)bh * NSEQ + ni) * HD + chunk * 8;
        *(uint4*)dst = *(const uint4*)tmp;
    }
}

// ---------------- Proj GEMM + bias + residual --------------------------------
#define PROJ_SMEM 98304
__global__ __launch_bounds__(256, 2) void proj_mm(const float* __restrict__ bias,
                                                  const float* __restrict__ z,
                                                  float* __restrict__ out) {
    float acc[4][4][4];
    const int m0 = blockIdx.y * 128, n0 = blockIdx.x * 128;
    gemm_core<4, 3>(g_oB, g_wprojT, m0, n0, acc);
    const int t = threadIdx.x, lane = t & 31, wid = t >> 5;
    const int wm = (wid >> 2) * 64, wn = (wid & 3) * 32;
#pragma unroll
    for (int mi = 0; mi < 4; mi++) {
        const int r = m0 + wm + mi * 16 + (lane >> 2);
#pragma unroll
        for (int nj = 0; nj < 4; nj++) {
            const int n = n0 + wn + nj * 8 + (lane & 3) * 2;
            const float2 b2 = *(const float2*)(bias + n);
            {
                const float2 z2 = *(const float2*)(z + (size_t)r * DM + n);
                float2 o; o.x = acc[mi][nj][0] + b2.x + z2.x;
                          o.y = acc[mi][nj][1] + b2.y + z2.y;
                *(float2*)(out + (size_t)r * DM + n) = o;
            }
            {
                const float2 z2 = *(const float2*)(z + (size_t)(r + 8) * DM + n);
                float2 o; o.x = acc[mi][nj][2] + b2.x + z2.x;
                          o.y = acc[mi][nj][3] + b2.y + z2.y;
                *(float2*)(out + (size_t)(r + 8) * DM + n) = o;
            }
        }
    }
}

// ---------------- Flash attention (mma.sync, 3-stage ring, 96KB) ------------
// 3 slots of 32KB (K 16KB + V 16KB). Q borrows slot 2's K area at startup,
// fragments extracted once, then slot 2 joins the ring. 2 CTAs/SM preserved.
#define ATT_SMEM (3 * 32768)
__global__ __launch_bounds__(256) void attn_mm() {
    extern __shared__ char sm[];
    const uint32_t sb = s2u(sm);
    const int t = threadIdx.x, lane = t & 31, wid = t >> 5;
    const int bh = blockIdx.y, q0 = blockIdx.x * 128;
    const __nv_bfloat16* Qp = g_q + ((size_t)bh * NSEQ + q0) * HD;
    const __nv_bfloat16* Kp = g_k + (size_t)bh * NSEQ * HD;
    const __nv_bfloat16* Vp = g_v + (size_t)bh * NSEQ * HD;

    auto load_tile = [&](uint32_t sbase, const __nv_bfloat16* gp) {
#pragma unroll
        for (int i = 0; i < 4; i++) {
            const int idx = t + i * 256, row = idx >> 3, ch = idx & 7;
            cp16(sbase + SWZ128(row, ch), gp + (size_t)row * HD + ch * 8);
        }
    };
    auto load_kv = [&](int kt, int slot) {
        load_tile(sb + slot * 32768, Kp + (size_t)kt * 128 * HD);
        load_tile(sb + slot * 32768 + 16384, Vp + (size_t)kt * 128 * HD);
    };
    load_tile(sb + 2 * 32768, Qp);             // Q borrows slot 2 K area
    load_kv(0, 0); CP_COMMIT();                // group 0: Q + KV0
    load_kv(1, 1); CP_COMMIT();                // group 1: KV1
    CP_WAIT(1);                                // group 0 done: Q + KV0 ready
    __syncthreads();

    uint32_t qf[4][4];
#pragma unroll
    for (int kk = 0; kk < 4; kk++)
        ldsm4(qf[kk], sb + 2 * 32768 +
                      SWZ128(wid * 16 + (lane & 15), kk * 2 + (lane >> 4)));
    __syncthreads();                           // all warps read Q before overwrite
    load_kv(2, 2); CP_COMMIT();                // group 2 overwrites Q area

    float o[8][4];
#pragma unroll
    for (int i = 0; i < 8; i++)
#pragma unroll
        for (int c = 0; c < 4; c++) o[i][c] = 0.f;
    float l0 = 0.f, l1 = 0.f;

    for (int kt = 0; kt < 16; kt++) {
        if (kt > 0) {
            if (kt < 15) CP_WAIT(1); else CP_WAIT(0);   // group kt complete
            __syncthreads();             // readers of slot (kt+2)%3 have passed
            if (kt + 2 < 16) { load_kv(kt + 2, (kt + 2) % 3); CP_COMMIT(); }
        }
        const uint32_t Kb = sb + (kt % 3) * 32768;
        const uint32_t Vb = Kb + 16384;
#pragma unroll
        for (int half = 0; half < 2; half++) {
            float s[8][4];
#pragma unroll
            for (int i = 0; i < 8; i++)
#pragma unroll
                for (int c = 0; c < 4; c++) s[i][c] = 0.f;
#pragma unroll
            for (int kk = 0; kk < 4; kk++) {          // S = Q @ K^T (16q x 64k)
                uint32_t bfr[4][4];
#pragma unroll
                for (int g = 0; g < 4; g++)
                    ldsm4(bfr[g], Kb + SWZ128(half * 64 + g * 16 + (lane & 7) +
                                              ((lane >> 4) << 3),
                                              kk * 2 + ((lane >> 3) & 1)));
#pragma unroll
                for (int nj = 0; nj < 8; nj++)
                    mma16816(s[nj], qf[kk], &bfr[nj >> 1][(nj & 1) * 2]);
            }
            uint32_t pf[4][4];                        // exp + pack P into A-frags
#pragma unroll
            for (int nj = 0; nj < 8; nj++) {
                const float p0 = __expf(s[nj][0]), p1 = __expf(s[nj][1]);
                const float p2 = __expf(s[nj][2]), p3 = __expf(s[nj][3]);
                l0 += p0 + p1; l1 += p2 + p3;
                const __nv_bfloat162 u = __floats2bfloat162_rn(p0, p1);
                const __nv_bfloat162 v = __floats2bfloat162_rn(p2, p3);
                pf[nj >> 1][(nj & 1) * 2 + 0] = *(const uint32_t*)&u;
                pf[nj >> 1][(nj & 1) * 2 + 1] = *(const uint32_t*)&v;
            }
#pragma unroll
            for (int kk = 0; kk < 4; kk++) {          // O += P @ V (k=16 keys)
                const int kb = (half * 4 + kk) * 16;
                uint32_t vf[4][4];
#pragma unroll
                for (int g = 0; g < 4; g++)
                    ldsm4t(vf[g], Vb + SWZ128(kb + (lane & 7) + (((lane >> 3) & 1) << 3),
                                              g * 2 + (lane >> 4)));
#pragma unroll
                for (int nj = 0; nj < 8; nj++)
                    mma16816(o[nj], pf[kk], &vf[nj >> 1][(nj & 1) * 2]);
            }
        }
    }
    l0 += __shfl_xor_sync(~0u, l0, 1); l0 += __shfl_xor_sync(~0u, l0, 2);
    l1 += __shfl_xor_sync(~0u, l1, 1); l1 += __shfl_xor_sync(~0u, l1, 2);
    const float i0 = 1.f / l0, i1 = 1.f / l1;
    const int bi = bh >> 4, h = bh & 15;
    const int r = q0 + wid * 16 + (lane >> 2);
#pragma unroll
    for (int nj = 0; nj < 8; nj++) {
        const int d = nj * 8 + (lane & 3) * 2;
        const __nv_bfloat162 u = __floats2bfloat162_rn(o[nj][0] * i0, o[nj][1] * i0);
        const __nv_bfloat162 v = __floats2bfloat162_rn(o[nj][2] * i1, o[nj][3] * i1);
        *(__nv_bfloat162*)(g_oB + (size_t)(bi * NSEQ + r) * DM + h * HD + d) = u;
        *(__nv_bfloat162*)(g_oB + (size_t)(bi * NSEQ + r + 8) * DM + h * HD + d) = v;
    }
}

// ---------------- launch ----------------------------------------------------
extern "C" void kernel_launch(void* const* d_in, const int* in_sizes, int n_in,
                              void* d_out, int out_size) {
    const float* z      = (const float*)d_in[0];
    const float* gamma  = (const float*)d_in[1];
    const float* beta   = (const float*)d_in[2];
    const float* w_qkv  = (const float*)d_in[3];
    const float* w_proj = (const float*)d_in[4];
    const float* b_proj = (const float*)d_in[5];
    float* out = (float*)d_out;

    cudaFuncSetAttribute(attn_mm, cudaFuncAttributeMaxDynamicSharedMemorySize, ATT_SMEM);
    cudaFuncSetAttribute(qkv_mm,  cudaFuncAttributeMaxDynamicSharedMemorySize, QKV_SMEM);
    cudaFuncSetAttribute(proj_mm, cudaFuncAttributeMaxDynamicSharedMemorySize, PROJ_SMEM);

    __nv_bfloat16 *wqT, *wpT;
    cudaGetSymbolAddress((void**)&wqT, g_wqkvT);
    cudaGetSymbolAddress((void**)&wpT, g_wprojT);

    ln_kernel<<<NTOK, 256>>>(z, gamma, beta);
    tcvt_kernel<<<dim3(NQKV / 32, DM / 32), dim3(32, 8)>>>(w_qkv, wqT, DM, NQKV);
    tcvt_kernel<<<dim3(DM / 32, DM / 32), dim3(32, 8)>>>(w_proj, wpT, DM, DM);
    qkv_mm<<<dim3(NH, NTOK / 128), 384, QKV_SMEM>>>();
    attn_mm<<<dim3(NSEQ / 128, BHN), 256, ATT_SMEM>>>();
    proj_mm<<<dim3(DM / 128, NTOK / 128), 256, PROJ_SMEM>>>(b_proj, z, out);
}

// round 13
// speedup vs baseline: 1.6700x; 1.1083x over previous
#include <cuda_runtime.h>
#include <cuda_bf16.h>
#include <cstdint>
#include <math.h>

#define DM    1024
#define NB    4
#define NSEQ  2048
#define NTOK  8192
#define NH    16
#define HD    64
#define BHN   64
#define NQKV  3072
#define LN_EPS 1e-5f
// q pre-scale: (1/8) * log2(e), so softmax uses ex2 directly
#define QSCALE 0.1803368801111204f

// ---------------- bf16 staging (device globals; no allocs allowed) ----------
__device__ __nv_bfloat16 g_znB[NTOK * DM];        // LN output bf16
__device__ __nv_bfloat16 g_wqkvT[NQKV * DM];      // w_qkv^T bf16 [out][in]
__device__ __nv_bfloat16 g_wprojT[DM * DM];       // w_proj^T bf16 [out][in]
__device__ __nv_bfloat16 g_q[BHN * NSEQ * HD];    // [bh][n][d], pre-scaled
__device__ __nv_bfloat16 g_k[BHN * NSEQ * HD];    // [bh][n][d]
__device__ __nv_bfloat16 g_v[BHN * NSEQ * HD];    // [bh][n][d]
__device__ __nv_bfloat16 g_oB[NTOK * DM];         // attn out bf16 [b][n][h*d]

// ---------------- baseline-PTX helpers (NO tcgen05 — compute_103 target) ----
__device__ __forceinline__ uint32_t s2u(const void* p) {
    return (uint32_t)__cvta_generic_to_shared(p);
}
__device__ __forceinline__ void cp16(uint32_t s, const void* g) {
    asm volatile("cp.async.cg.shared.global [%0], [%1], 16;" :: "r"(s), "l"(g));
}
#define CP_COMMIT() asm volatile("cp.async.commit_group;" ::: "memory")
#define CP_WAIT(n)  asm volatile("cp.async.wait_group %0;" :: "n"(n) : "memory")

__device__ __forceinline__ void ldsm4(uint32_t* r, uint32_t a) {
    asm volatile("ldmatrix.sync.aligned.m8n8.x4.shared.b16 {%0,%1,%2,%3}, [%4];"
                 : "=r"(r[0]), "=r"(r[1]), "=r"(r[2]), "=r"(r[3]) : "r"(a));
}
__device__ __forceinline__ void ldsm4t(uint32_t* r, uint32_t a) {
    asm volatile("ldmatrix.sync.aligned.m8n8.x4.trans.shared.b16 {%0,%1,%2,%3}, [%4];"
                 : "=r"(r[0]), "=r"(r[1]), "=r"(r[2]), "=r"(r[3]) : "r"(a));
}
__device__ __forceinline__ void mma16816(float* d, const uint32_t* a, const uint32_t* b) {
    asm volatile("mma.sync.aligned.m16n8k16.row.col.f32.bf16.bf16.f32 "
                 "{%0,%1,%2,%3}, {%4,%5,%6,%7}, {%8,%9}, {%0,%1,%2,%3};"
                 : "+f"(d[0]), "+f"(d[1]), "+f"(d[2]), "+f"(d[3])
                 : "r"(a[0]), "r"(a[1]), "r"(a[2]), "r"(a[3]), "r"(b[0]), "r"(b[1]));
}
__device__ __forceinline__ float fexp2(float x) {
    float y;
    asm("ex2.approx.ftz.f32 %0, %1;" : "=f"(y) : "f"(x));
    return y;
}
#define SWZ128(row, chunk) ((row) * 128 + ((((chunk) ^ ((row) & 7))) << 4))

// ---------------- LayerNorm -> bf16 -----------------------------------------
__global__ __launch_bounds__(256) void ln_kernel(const float* __restrict__ z,
                                                 const float* __restrict__ gamma,
                                                 const float* __restrict__ beta) {
    __shared__ float rs[8], rss[8];
    const int row = blockIdx.x, t = threadIdx.x;
    const float4 v = *(const float4*)(z + (size_t)row * DM + t * 4);
    float s = v.x + v.y + v.z + v.w;
    float ss = v.x * v.x + v.y * v.y + v.z * v.z + v.w * v.w;
#pragma unroll
    for (int off = 16; off; off >>= 1) {
        s  += __shfl_xor_sync(~0u, s, off);
        ss += __shfl_xor_sync(~0u, ss, off);
    }
    const int w = t >> 5, lane = t & 31;
    if (lane == 0) { rs[w] = s; rss[w] = ss; }
    __syncthreads();
    if (w == 0) {
        float s2 = (lane < 8) ? rs[lane] : 0.f, ss2 = (lane < 8) ? rss[lane] : 0.f;
#pragma unroll
        for (int off = 4; off; off >>= 1) {
            s2  += __shfl_xor_sync(~0u, s2, off, 8);
            ss2 += __shfl_xor_sync(~0u, ss2, off, 8);
        }
        if (lane == 0) { rs[0] = s2; rss[0] = ss2; }
    }
    __syncthreads();
    const float mean = rs[0] * (1.f / DM);
    const float var  = rss[0] * (1.f / DM) - mean * mean;
    const float inv  = rsqrtf(var + LN_EPS);
    const float4 g = *(const float4*)(gamma + t * 4);
    const float4 b = *(const float4*)(beta + t * 4);
    __nv_bfloat162 p0 = __floats2bfloat162_rn((v.x - mean) * inv * g.x + b.x,
                                              (v.y - mean) * inv * g.y + b.y);
    __nv_bfloat162 p1 = __floats2bfloat162_rn((v.z - mean) * inv * g.z + b.z,
                                              (v.w - mean) * inv * g.w + b.w);
    __nv_bfloat162* dst = (__nv_bfloat162*)(g_znB + (size_t)row * DM + t * 4);
    dst[0] = p0; dst[1] = p1;
}

// ---------------- weight transpose + fp32->bf16 -----------------------------
__global__ __launch_bounds__(256) void tcvt_kernel(const float* __restrict__ w,
                                                   __nv_bfloat16* __restrict__ wT,
                                                   int K, int N) {
    __shared__ float tile[32][33];
    const int n0 = blockIdx.x * 32, k0 = blockIdx.y * 32;
    for (int i = threadIdx.y; i < 32; i += 8)
        tile[i][threadIdx.x] = w[(size_t)(k0 + i) * N + n0 + threadIdx.x];
    __syncthreads();
    for (int i = threadIdx.y; i < 32; i += 8)
        wT[(size_t)(n0 + i) * K + k0 + threadIdx.x] = __float2bfloat16(tile[threadIdx.x][i]);
}

// ---------------- templated 128xBN GEMM core (NS-stage, K-chunk 64) ---------
// WC = warp columns. Warps = 2 x WC, threads = 64*WC, BN = 32*WC.
// Burst cp.async per stage (one commit), one __syncthreads per chunk.
template<int WC, int NS>
__device__ __forceinline__ void gemm_core(const __nv_bfloat16* __restrict__ gA,
                                          const __nv_bfloat16* __restrict__ gB,
                                          int m0, int n0, float acc[4][4][4]) {
    constexpr int NT = 64 * WC;
    constexpr int BN = 32 * WC;
    constexpr int ABYTES = 16384;
    constexpr int STAGE  = ABYTES + BN * 128;
    constexpr int TOT    = (128 + BN) * 8;     // 16B chunks per stage
    constexpr int NLOAD  = (TOT + NT - 1) / NT;
    extern __shared__ char sm[];
    const uint32_t sb = s2u(sm);
    const int t = threadIdx.x, lane = t & 31, wid = t >> 5;
    const int wm = (wid / WC) * 64, wn = (wid % WC) * 32;
#pragma unroll
    for (int i = 0; i < 4; i++)
#pragma unroll
        for (int j = 0; j < 4; j++)
#pragma unroll
            for (int c = 0; c < 4; c++) acc[i][j][c] = 0.f;

    auto load_stage = [&](int kt, int slot) {
        const int k0 = kt * 64;
        const uint32_t base = sb + slot * STAGE;
#pragma unroll
        for (int i = 0; i < NLOAD; i++) {
            const int idx = t + i * NT;
            if ((TOT % NT == 0) || idx < TOT) {
                const int row = idx >> 3, ch = idx & 7;
                if (row < 128)
                    cp16(base + SWZ128(row, ch),
                         gA + (size_t)(m0 + row) * DM + k0 + ch * 8);
                else
                    cp16(base + ABYTES + SWZ128((row - 128), ch),
                         gB + (size_t)(n0 + row - 128) * DM + k0 + ch * 8);
            }
        }
    };
#pragma unroll
    for (int s = 0; s < NS - 1; s++) { load_stage(s, s); CP_COMMIT(); }
    for (int kt = 0; kt < 16; kt++) {
        // stage kt must be complete; allow min(NS-2, 15-kt) groups pending
        if constexpr (NS == 4) {
            if (kt < 14) CP_WAIT(2); else if (kt == 14) CP_WAIT(1); else CP_WAIT(0);
        } else {
            if (kt < 15) CP_WAIT(1); else CP_WAIT(0);
        }
        __syncthreads();                 // stage kt ready; slot (kt+NS-1)%NS free
        if (kt + NS - 1 < 16) { load_stage(kt + NS - 1, (kt + NS - 1) % NS); CP_COMMIT(); }
        const uint32_t Ab = sb + (kt % NS) * STAGE;
        const uint32_t Bb = Ab + ABYTES;
#pragma unroll
        for (int k16 = 0; k16 < 4; k16++) {
            uint32_t af[4][4], bfr[2][4];
#pragma unroll
            for (int mi = 0; mi < 4; mi++)
                ldsm4(af[mi], Ab + SWZ128(wm + mi * 16 + (lane & 15),
                                          k16 * 2 + (lane >> 4)));
#pragma unroll
            for (int g = 0; g < 2; g++)
                ldsm4(bfr[g], Bb + SWZ128(wn + g * 16 + (lane & 7) + ((lane >> 4) << 3),
                                          k16 * 2 + ((lane >> 3) & 1)));
#pragma unroll
            for (int mi = 0; mi < 4; mi++)
#pragma unroll
                for (int nj = 0; nj < 4; nj++)
                    mma16816(acc[mi][nj], af[mi], &bfr[nj >> 1][(nj & 1) * 2]);
        }
    }
}

// ---------------- QKV GEMM: N-tile 192 == one head; coalesced epilogue ------
// smem: 4 stages x (16384 + 24576) = 163840; epilogue staging reuses 51200 B.
#define QKV_SMEM 163840
__global__ __launch_bounds__(384, 1) void qkv_mm() {
    float acc[4][4][4];
    const int h = blockIdx.x, m0 = blockIdx.y * 128;
    gemm_core<6, 4>(g_znB, g_wqkvT, m0, h * 192, acc);

    extern __shared__ char sm[];
    const int t = threadIdx.x, lane = t & 31, wid = t >> 5;
    const int wm = (wid / 6) * 64, wn = (wid % 6) * 32;
    __syncthreads();                           // all MMA reads of smem done
    // stage bf16 tile [128 m][192 c], pitch 400 B (conflict-free stores)
#pragma unroll
    for (int mi = 0; mi < 4; mi++)
#pragma unroll
        for (int nj = 0; nj < 4; nj++)
#pragma unroll
            for (int half = 0; half < 2; half++) {
                const int er = wm + mi * 16 + (lane >> 2) + half * 8;
                const int ec = wn + nj * 8 + (lane & 3) * 2;
                __nv_bfloat162 p = __floats2bfloat162_rn(acc[mi][nj][half * 2],
                                                         acc[mi][nj][half * 2 + 1]);
                *(__nv_bfloat162*)(sm + er * 400 + ec * 2) = p;
            }
    __syncthreads();
    // gather stride-3, write coalesced 16B vectors. tasks = 128m x 3sel x 8chunks
#pragma unroll
    for (int i = 0; i < 8; i++) {
        const int task = t + i * 384;
        const int chunk = task & 7;
        const int ms = task >> 3;
        const int sel = ms % 3;
        const int m = ms / 3;
        const int mg = m0 + m, bi = mg >> 11, ni = mg & 2047;
        const int bh = bi * NH + h;
        __align__(16) __nv_bfloat16 tmp[8];
#pragma unroll
        for (int j = 0; j < 8; j++) {
            __nv_bfloat16 v = *(const __nv_bfloat16*)(sm + m * 400 +
                                                      (3 * (chunk * 8 + j) + sel) * 2);
            tmp[j] = (sel == 0) ? __float2bfloat16(__bfloat162float(v) * QSCALE) : v;
        }
        __nv_bfloat16* dst = (sel == 0 ? g_q : sel == 1 ? g_k : g_v)
                             + ((size_t)bh * NSEQ + ni) * HD + chunk * 8;
        *(uint4*)dst = *(const uint4*)tmp;
    }
}

// ---------------- Proj GEMM + bias + residual --------------------------------
#define PROJ_SMEM 98304
__global__ __launch_bounds__(256, 2) void proj_mm(const float* __restrict__ bias,
                                                  const float* __restrict__ z,
                                                  float* __restrict__ out) {
    float acc[4][4][4];
    const int m0 = blockIdx.y * 128, n0 = blockIdx.x * 128;
    gemm_core<4, 3>(g_oB, g_wprojT, m0, n0, acc);
    const int t = threadIdx.x, lane = t & 31, wid = t >> 5;
    const int wm = (wid >> 2) * 64, wn = (wid & 3) * 32;
#pragma unroll
    for (int mi = 0; mi < 4; mi++) {
        const int r = m0 + wm + mi * 16 + (lane >> 2);
#pragma unroll
        for (int nj = 0; nj < 4; nj++) {
            const int n = n0 + wn + nj * 8 + (lane & 3) * 2;
            const float2 b2 = *(const float2*)(bias + n);
            {
                const float2 z2 = *(const float2*)(z + (size_t)r * DM + n);
                float2 o; o.x = acc[mi][nj][0] + b2.x + z2.x;
                          o.y = acc[mi][nj][1] + b2.y + z2.y;
                *(float2*)(out + (size_t)r * DM + n) = o;
            }
            {
                const float2 z2 = *(const float2*)(z + (size_t)(r + 8) * DM + n);
                float2 o; o.x = acc[mi][nj][2] + b2.x + z2.x;
                          o.y = acc[mi][nj][3] + b2.y + z2.y;
                *(float2*)(out + (size_t)(r + 8) * DM + n) = o;
            }
        }
    }
}

// ---------------- Flash attention (mma.sync, 3-stage ring, 96KB) ------------
// 3 slots of 32KB (K 16KB + V 16KB). Q borrows slot 2's K area at startup,
// fragments extracted once, then slot 2 joins the ring. 2 CTAs/SM forced.
// Softmax: p = 2^s (log2e folded into q scale), no max-tracking.
#define ATT_SMEM (3 * 32768)
__global__ __launch_bounds__(256, 2) void attn_mm() {
    extern __shared__ char sm[];
    const uint32_t sb = s2u(sm);
    const int t = threadIdx.x, lane = t & 31, wid = t >> 5;
    const int bh = blockIdx.y, q0 = blockIdx.x * 128;
    const __nv_bfloat16* Qp = g_q + ((size_t)bh * NSEQ + q0) * HD;
    const __nv_bfloat16* Kp = g_k + (size_t)bh * NSEQ * HD;
    const __nv_bfloat16* Vp = g_v + (size_t)bh * NSEQ * HD;

    auto load_tile = [&](uint32_t sbase, const __nv_bfloat16* gp) {
#pragma unroll
        for (int i = 0; i < 4; i++) {
            const int idx = t + i * 256, row = idx >> 3, ch = idx & 7;
            cp16(sbase + SWZ128(row, ch), gp + (size_t)row * HD + ch * 8);
        }
    };
    auto load_kv = [&](int kt, int slot) {
        load_tile(sb + slot * 32768, Kp + (size_t)kt * 128 * HD);
        load_tile(sb + slot * 32768 + 16384, Vp + (size_t)kt * 128 * HD);
    };
    load_tile(sb + 2 * 32768, Qp);             // Q borrows slot 2 K area
    load_kv(0, 0); CP_COMMIT();                // group 0: Q + KV0
    load_kv(1, 1); CP_COMMIT();                // group 1: KV1
    CP_WAIT(1);                                // group 0 done: Q + KV0 ready
    __syncthreads();

    uint32_t qf[4][4];
#pragma unroll
    for (int kk = 0; kk < 4; kk++)
        ldsm4(qf[kk], sb + 2 * 32768 +
                      SWZ128(wid * 16 + (lane & 15), kk * 2 + (lane >> 4)));
    __syncthreads();                           // all warps read Q before overwrite
    load_kv(2, 2); CP_COMMIT();                // group 2 overwrites Q area

    float o[8][4];
#pragma unroll
    for (int i = 0; i < 8; i++)
#pragma unroll
        for (int c = 0; c < 4; c++) o[i][c] = 0.f;
    float l0 = 0.f, l1 = 0.f;

    for (int kt = 0; kt < 16; kt++) {
        if (kt > 0) {
            if (kt < 15) CP_WAIT(1); else CP_WAIT(0);   // group kt complete
            __syncthreads();             // readers of slot (kt+2)%3 have passed
            if (kt + 2 < 16) { load_kv(kt + 2, (kt + 2) % 3); CP_COMMIT(); }
        }
        const uint32_t Kb = sb + (kt % 3) * 32768;
        const uint32_t Vb = Kb + 16384;
#pragma unroll
        for (int half = 0; half < 2; half++) {
            float s[8][4];
#pragma unroll
            for (int i = 0; i < 8; i++)
#pragma unroll
                for (int c = 0; c < 4; c++) s[i][c] = 0.f;
#pragma unroll
            for (int kk = 0; kk < 4; kk++) {          // S = Q @ K^T (16q x 64k)
                uint32_t bfr[4][4];
#pragma unroll
                for (int g = 0; g < 4; g++)
                    ldsm4(bfr[g], Kb + SWZ128(half * 64 + g * 16 + (lane & 7) +
                                              ((lane >> 4) << 3),
                                              kk * 2 + ((lane >> 3) & 1)));
#pragma unroll
                for (int nj = 0; nj < 8; nj++)
                    mma16816(s[nj], qf[kk], &bfr[nj >> 1][(nj & 1) * 2]);
            }
            uint32_t pf[4][4];                        // p = 2^s + pack A-frags
#pragma unroll
            for (int nj = 0; nj < 8; nj++) {
                const float p0 = fexp2(s[nj][0]), p1 = fexp2(s[nj][1]);
                const float p2 = fexp2(s[nj][2]), p3 = fexp2(s[nj][3]);
                l0 += p0 + p1; l1 += p2 + p3;
                const __nv_bfloat162 u = __floats2bfloat162_rn(p0, p1);
                const __nv_bfloat162 v = __floats2bfloat162_rn(p2, p3);
                pf[nj >> 1][(nj & 1) * 2 + 0] = *(const uint32_t*)&u;
                pf[nj >> 1][(nj & 1) * 2 + 1] = *(const uint32_t*)&v;
            }
#pragma unroll
            for (int kk = 0; kk < 4; kk++) {          // O += P @ V (k=16 keys)
                const int kb = (half * 4 + kk) * 16;
                uint32_t vf[4][4];
#pragma unroll
                for (int g = 0; g < 4; g++)
                    ldsm4t(vf[g], Vb + SWZ128(kb + (lane & 7) + (((lane >> 3) & 1) << 3),
                                              g * 2 + (lane >> 4)));
#pragma unroll
                for (int nj = 0; nj < 8; nj++)
                    mma16816(o[nj], pf[kk], &vf[nj >> 1][(nj & 1) * 2]);
            }
        }
    }
    l0 += __shfl_xor_sync(~0u, l0, 1); l0 += __shfl_xor_sync(~0u, l0, 2);
    l1 += __shfl_xor_sync(~0u, l1, 1); l1 += __shfl_xor_sync(~0u, l1, 2);
    const float i0 = 1.f / l0, i1 = 1.f / l1;
    const int bi = bh >> 4, h = bh & 15;
    const int r = q0 + wid * 16 + (lane >> 2);
#pragma unroll
    for (int nj = 0; nj < 8; nj++) {
        const int d = nj * 8 + (lane & 3) * 2;
        const __nv_bfloat162 u = __floats2bfloat162_rn(o[nj][0] * i0, o[nj][1] * i0);
        const __nv_bfloat162 v = __floats2bfloat162_rn(o[nj][2] * i1, o[nj][3] * i1);
        *(__nv_bfloat162*)(g_oB + (size_t)(bi * NSEQ + r) * DM + h * HD + d) = u;
        *(__nv_bfloat162*)(g_oB + (size_t)(bi * NSEQ + r + 8) * DM + h * HD + d) = v;
    }
}

// ---------------- launch ----------------------------------------------------
extern "C" void kernel_launch(void* const* d_in, const int* in_sizes, int n_in,
                              void* d_out, int out_size) {
    const float* z      = (const float*)d_in[0];
    const float* gamma  = (const float*)d_in[1];
    const float* beta   = (const float*)d_in[2];
    const float* w_qkv  = (const float*)d_in[3];
    const float* w_proj = (const float*)d_in[4];
    const float* b_proj = (const float*)d_in[5];
    float* out = (float*)d_out;

    cudaFuncSetAttribute(attn_mm, cudaFuncAttributeMaxDynamicSharedMemorySize, ATT_SMEM);
    cudaFuncSetAttribute(qkv_mm,  cudaFuncAttributeMaxDynamicSharedMemorySize, QKV_SMEM);
    cudaFuncSetAttribute(proj_mm, cudaFuncAttributeMaxDynamicSharedMemorySize, PROJ_SMEM);

    __nv_bfloat16 *wqT, *wpT;
    cudaGetSymbolAddress((void**)&wqT, g_wqkvT);
    cudaGetSymbolAddress((void**)&wpT, g_wprojT);

    ln_kernel<<<NTOK, 256>>>(z, gamma, beta);
    tcvt_kernel<<<dim3(NQKV / 32, DM / 32), dim3(32, 8)>>>(w_qkv, wqT, DM, NQKV);
    tcvt_kernel<<<dim3(DM / 32, DM / 32), dim3(32, 8)>>>(w_proj, wpT, DM, DM);
    qkv_mm<<<dim3(NH, NTOK / 128), 384, QKV_SMEM>>>();
    attn_mm<<<dim3(NSEQ / 128, BHN), 256, ATT_SMEM>>>();
    proj_mm<<<dim3(DM / 128, NTOK / 128), 256, PROJ_SMEM>>>(b_proj, z, out);
}